// round 1
// baseline (speedup 1.0000x reference)
#include <cuda_runtime.h>
#include <cuda_bf16.h>

#define N_CELLS   776
#define N_ANCHORS 3
#define N_CH      7
#define CONF_THRESH 0.8f
#define NO_OBJECT   0.5f

// One block, 800 threads (25 warps), one thread per cell (774..799 idle-ish).
// Deterministic reduction: warp shuffle -> shared partials -> thread 0 serial sum.
__global__ __launch_bounds__(800, 1)
void yolo_loss_kernel(const float* __restrict__ pred,
                      const float* __restrict__ label,
                      float* __restrict__ out)
{
    const int cell = threadIdx.x;

    // Broadcast label into registers (L1 hit after first warp).
    const float lx = __ldg(&label[0]);
    const float ly = __ldg(&label[1]);
    const float lw = __ldg(&label[2]);
    const float lh = __ldg(&label[3]);
    const float lc = __ldg(&label[4]);
    const float l5 = __ldg(&label[5]);
    const float l6 = __ldg(&label[6]);

    const float lw2 = lw * 0.5f, lh2 = lh * 0.5f;
    const float area_b = fabsf(lw * lh);

    float loss = 0.0f;

    if (cell < N_CELLS) {
        const float* base = pred + (size_t)cell * (N_ANCHORS * N_CH);

        float best_iou = -1.0f;
        float b0 = 0.f, b1 = 0.f, b4 = 0.f, b5 = 0.f, b6 = 0.f;

        #pragma unroll
        for (int a = 0; a < N_ANCHORS; ++a) {
            const float* p = base + a * N_CH;
            // 7 floats: x y w h conf c5 c6
            float px = p[0], py = p[1], pw = p[2], ph = p[3];
            float pc = p[4], p5 = p[5], p6 = p[6];

            float pw2 = pw * 0.5f, ph2 = ph * 0.5f;
            float ax = fmaxf(px - pw2, lx - lw2);
            float ay = fmaxf(py - ph2, ly - lh2);
            float bx = fminf(px + pw2, lx + lw2);
            float by = fminf(py + ph2, ly + lh2);
            float inter = fabsf(fmaxf(bx - ax, 0.0f) * fmaxf(by - ay, 0.0f));
            float area_a = fabsf(pw * ph);
            float iou = inter / (area_a + area_b - inter);

            // jnp.argmax keeps the FIRST max on ties -> strict >
            if (iou > best_iou) {
                best_iou = iou;
                b0 = px; b1 = py; b4 = pc; b5 = p5; b6 = p6;
            }
        }

        float dx = lx - b0, dy = ly - b1;
        float xy_loss = dx * dx + dy * dy;
        // Reference uses sqrt(label[0]), sqrt(label[1]) vs best[:,0], best[:,1]
        float swx = sqrtf(lx) - sqrtf(b0);
        float swy = sqrtf(ly) - sqrtf(b1);
        float wh_loss = swx * swx + swy * swy;
        float coord_loss = xy_loss + wh_loss;

        bool has_obj = b4 > CONF_THRESH;
        float d5 = l5 - b5, d6 = l6 - b6;
        float class_loss = has_obj ? (d5 * d5 + d6 * d6) : 0.0f;
        float dc = lc - b4;
        float conf_sq = dc * dc;
        float conf_loss = has_obj ? conf_sq : NO_OBJECT * conf_sq;

        loss = coord_loss + class_loss + conf_loss;
    }

    // Deterministic reduction: butterfly within warp (fixed order), then
    // thread 0 serially sums the 25 warp partials.
    #pragma unroll
    for (int off = 16; off > 0; off >>= 1)
        loss += __shfl_down_sync(0xFFFFFFFFu, loss, off);

    __shared__ float warp_sums[25];
    const int warp = threadIdx.x >> 5;
    const int lane = threadIdx.x & 31;
    if (lane == 0) warp_sums[warp] = loss;
    __syncthreads();

    if (threadIdx.x == 0) {
        float total = 0.0f;
        #pragma unroll
        for (int w = 0; w < 25; ++w) total += warp_sums[w];
        out[0] = total;
    }
}

extern "C" void kernel_launch(void* const* d_in, const int* in_sizes, int n_in,
                              void* d_out, int out_size)
{
    const float* pred  = (const float*)d_in[0];
    const float* label = (const float*)d_in[1];
    float* out = (float*)d_out;
    yolo_loss_kernel<<<1, 800>>>(pred, label, out);
}